// round 1
// baseline (speedup 1.0000x reference)
#include <cuda_runtime.h>
#include <math.h>
#include <stdint.h>

#define N_LEVELS 16
#define N_POINTS 524288
#define HASH_MASK 0x7FFFFu       // hashed level size = 2^19 exactly
#define P1 2654435761u
#define P2 805459861u

// Dense-level resolutions: res_l = ceil(16 * 2^(7l/15)); levels 0..4 are dense
// (res^3 <= 2^19). Values 16,23,31,43,59 — each ceil argument is >0.1 away from
// an integer, so no libm-rounding risk.
__constant__ unsigned c_res[5] = {16u, 23u, 31u, 43u, 59u};

struct Scales { float s[N_LEVELS]; };

__global__ __launch_bounds__(256) void hashenc_kernel(
    const float*  __restrict__ inputs,     // [N_POINTS, 3]
    const float2* __restrict__ emb,        // [total_entries] of float2
    const int*    __restrict__ offs,       // [17]
    float2*       __restrict__ out,        // [N_POINTS * 16] float2
    Scales sc)
{
    unsigned t = blockIdx.x * blockDim.x + threadIdx.x;
    unsigned level = t & 15u;
    unsigned point = t >> 4;

    // Coordinates (16 consecutive threads share a point -> L1 broadcast)
    float x = __ldg(&inputs[point * 3 + 0]);
    float y = __ldg(&inputs[point * 3 + 1]);
    float z = __ldg(&inputs[point * 3 + 2]);

    float scale = sc.s[level];
    // pos must be a plain fp32 multiply (matches jnp inputs*scale bit-exactly)
    float px = x * scale, py = y * scale, pz = z * scale;
    float fx0 = floorf(px), fy0 = floorf(py), fz0 = floorf(pz);
    float fx = px - fx0, fy = py - fy0, fz = pz - fz0;
    unsigned gx = (unsigned)fx0, gy = (unsigned)fy0, gz = (unsigned)fz0;

    unsigned base = (unsigned)__ldg(&offs[level]);

    unsigned idx[8];
    if (level >= 5u) {
        // hashed: idx = (cx*1 ^ cy*P1 ^ cz*P2) & (2^19-1)
        unsigned hy0 = gy * P1, hy1 = hy0 + P1;
        unsigned hz0 = gz * P2, hz1 = hz0 + P2;
        unsigned x0 = gx, x1 = gx + 1u;
        unsigned s00 = hy0 ^ hz0, s10 = hy1 ^ hz0;
        unsigned s01 = hy0 ^ hz1, s11 = hy1 ^ hz1;
        idx[0] = (x0 ^ s00) & HASH_MASK;
        idx[1] = (x1 ^ s00) & HASH_MASK;
        idx[2] = (x0 ^ s10) & HASH_MASK;
        idx[3] = (x1 ^ s10) & HASH_MASK;
        idx[4] = (x0 ^ s01) & HASH_MASK;
        idx[5] = (x1 ^ s01) & HASH_MASK;
        idx[6] = (x0 ^ s11) & HASH_MASK;
        idx[7] = (x1 ^ s11) & HASH_MASK;
    } else {
        // dense: row-major within res^3, corners clamped to res-1
        unsigned res = c_res[level];
        unsigned rm1 = res - 1u;
        unsigned x0 = min(gx, rm1),      x1 = min(gx + 1u, rm1);
        unsigned y0 = min(gy, rm1) * res, y1 = min(gy + 1u, rm1) * res;
        unsigned rr = res * res;
        unsigned z0 = min(gz, rm1) * rr, z1 = min(gz + 1u, rm1) * rr;
        idx[0] = x0 + y0 + z0;
        idx[1] = x1 + y0 + z0;
        idx[2] = x0 + y1 + z0;
        idx[3] = x1 + y1 + z0;
        idx[4] = x0 + y0 + z1;
        idx[5] = x1 + y0 + z1;
        idx[6] = x0 + y1 + z1;
        idx[7] = x0 + y0 + z1;  // placeholder overwritten below (keep symmetry)
        idx[6] = x0 + y1 + z1;
        idx[7] = x1 + y1 + z1;
    }

    // Issue all 8 gathers first (MLP=8). x-adjacent corner pairs often share a
    // 32B sector -> second load is an L1 hit.
    float2 e[8];
#pragma unroll
    for (int c = 0; c < 8; c++)
        e[c] = __ldg(&emb[base + idx[c]]);

    float wx[2] = {1.0f - fx, fx};
    float wy[2] = {1.0f - fy, fy};
    float wz[2] = {1.0f - fz, fz};

    float ox = 0.0f, oy = 0.0f;
#pragma unroll
    for (int c = 0; c < 8; c++) {
        float w = wx[c & 1] * wy[(c >> 1) & 1] * wz[(c >> 2) & 1];
        ox += w * e[c].x;
        oy += w * e[c].y;
    }

    out[t] = make_float2(ox, oy);
}

extern "C" void kernel_launch(void* const* d_in, const int* in_sizes, int n_in,
                              void* d_out, int out_size)
{
    const float*  inputs = (const float*)d_in[0];
    const float2* emb    = (const float2*)d_in[1];
    const int*    offs   = (const int*)d_in[2];
    float2*       out    = (float2*)d_out;

    // scale[l] = float32(16 * (2^(7/15))^l), computed in double so the float32
    // cast absorbs any sub-ulp libm difference vs numpy.
    Scales sc;
    double ratio = exp2(7.0 / 15.0);
    for (int l = 0; l < N_LEVELS; l++)
        sc.s[l] = (float)(16.0 * pow(ratio, (double)l));

    unsigned total = (unsigned)N_POINTS * N_LEVELS;   // 8388608 threads
    dim3 block(256);
    dim3 grid(total / 256);
    hashenc_kernel<<<grid, block>>>(inputs, emb, offs, out, sc);
}

// round 2
// speedup vs baseline: 1.0032x; 1.0032x over previous
#include <cuda_runtime.h>
#include <math.h>
#include <stdint.h>

#define N_LEVELS 16
#define N_POINTS 524288
#define HASH_MASK 0x7FFFFu       // hashed level size = 2^19 exactly
#define P1 2654435761u
#define P2 805459861u

// Dense-level resolutions: res_l = ceil(16 * 2^(7l/15)); levels 0..4 are dense
// (res^3 <= 2^19): 16, 23, 31, 43, 59.
__constant__ unsigned c_res[5] = {16u, 23u, 31u, 43u, 59u};

struct Scales { float s[N_LEVELS]; };

__global__ __launch_bounds__(256) void hashenc_kernel(
    const float*  __restrict__ inputs,     // [N_POINTS, 3]
    const float2* __restrict__ emb,        // [total_entries] of float2
    const int*    __restrict__ offs,       // [17]
    float2*       __restrict__ out,        // [N_POINTS * 16] float2
    Scales sc)
{
    unsigned t = blockIdx.x * blockDim.x + threadIdx.x;
    unsigned level = t & 15u;
    unsigned point = t >> 4;

    // Coordinates (16 consecutive threads share a point -> L1 broadcast)
    float x = __ldg(&inputs[point * 3 + 0]);
    float y = __ldg(&inputs[point * 3 + 1]);
    float z = __ldg(&inputs[point * 3 + 2]);

    float scale = sc.s[level];
    // plain fp32 multiply (matches jnp inputs*scale bit-exactly)
    float px = x * scale, py = y * scale, pz = z * scale;
    float fx0 = floorf(px), fy0 = floorf(py), fz0 = floorf(pz);
    float fx = px - fx0, fy = py - fy0, fz = pz - fz0;
    unsigned gx = (unsigned)fx0, gy = (unsigned)fy0, gz = (unsigned)fz0;

    unsigned base = (unsigned)__ldg(&offs[level]);

    // Absolute embedding indices for the 4 (y,z) corner pairs:
    // a0[k] = index of (x0, yz_k), a1[k] = index of (x1, yz_k)
    unsigned a0[4], a1[4];
    if (level >= 5u) {
        // hashed: idx = (cx*1 ^ cy*P1 ^ cz*P2) & (2^19-1)
        unsigned hy0 = gy * P1, hy1 = hy0 + P1;
        unsigned hz0 = gz * P2, hz1 = hz0 + P2;
        unsigned s0 = hy0 ^ hz0, s1 = hy1 ^ hz0;
        unsigned s2 = hy0 ^ hz1, s3 = hy1 ^ hz1;
        unsigned ss[4] = {s0, s1, s2, s3};
#pragma unroll
        for (int k = 0; k < 4; k++) {
            a0[k] = base + ((gx        ^ ss[k]) & HASH_MASK);
            a1[k] = base + (((gx + 1u) ^ ss[k]) & HASH_MASK);
        }
    } else {
        // dense: row-major within res^3, corners clamped to res-1
        unsigned res = c_res[level];
        unsigned rm1 = res - 1u;
        unsigned rr  = res * res;
        unsigned x0 = min(gx, rm1),         x1 = min(gx + 1u, rm1);
        unsigned y0 = min(gy, rm1) * res,   y1 = min(gy + 1u, rm1) * res;
        unsigned z0 = min(gz, rm1) * rr,    z1 = min(gz + 1u, rm1) * rr;
        unsigned yz[4] = {y0 + z0, y1 + z0, y0 + z1, y1 + z1};
#pragma unroll
        for (int k = 0; k < 4; k++) {
            a0[k] = base + x0 + yz[k];
            a1[k] = base + x1 + yz[k];
        }
    }

    // Unconditional aligned float4 at a0&~1: covers the float2 at a0 AND,
    // when (a0^a1)==1 (adjacent aligned pair), the float2 at a1 too — one
    // L1 access instead of two. Same cache line as a0 otherwise (no extra
    // cost). Issue all 4 first for MLP.
    float4 v4[4];
#pragma unroll
    for (int k = 0; k < 4; k++)
        v4[k] = __ldg((const float4*)(emb + (a0[k] & ~1u)));

    // Predicated second load only for non-adjacent pairs (~50% on hashed
    // levels when gx is odd; ~50% on dense when a0 is odd).
    bool adj[4];
    float2 e1ld[4];
#pragma unroll
    for (int k = 0; k < 4; k++) {
        adj[k] = ((a0[k] ^ a1[k]) == 1u);
        if (!adj[k]) e1ld[k] = __ldg(&emb[a1[k]]);
    }

    float wx0 = 1.0f - fx, wx1 = fx;
    float wy_[2] = {1.0f - fy, fy};
    float wz_[2] = {1.0f - fz, fz};

    float ox = 0.0f, oy = 0.0f;
#pragma unroll
    for (int k = 0; k < 4; k++) {
        float2 lo = make_float2(v4[k].x, v4[k].y);
        float2 hi = make_float2(v4[k].z, v4[k].w);
        float2 e0 = (a0[k] & 1u) ? hi : lo;
        float2 e1 = adj[k] ? ((a1[k] & 1u) ? hi : lo) : e1ld[k];
        float wyz = wy_[k & 1] * wz_[k >> 1];
        ox += wyz * (wx0 * e0.x + wx1 * e1.x);
        oy += wyz * (wx0 * e0.y + wx1 * e1.y);
    }

    // Streaming store: keep the 67MB output from evicting the ~49MB
    // embedding table out of L2.
    __stcs(&out[t], make_float2(ox, oy));
}

extern "C" void kernel_launch(void* const* d_in, const int* in_sizes, int n_in,
                              void* d_out, int out_size)
{
    const float*  inputs = (const float*)d_in[0];
    const float2* emb    = (const float2*)d_in[1];
    const int*    offs   = (const int*)d_in[2];
    float2*       out    = (float2*)d_out;

    // scale[l] = float32(16 * (2^(7/15))^l), computed in double so the float32
    // cast absorbs any sub-ulp libm difference vs numpy.
    Scales sc;
    double ratio = exp2(7.0 / 15.0);
    for (int l = 0; l < N_LEVELS; l++)
        sc.s[l] = (float)(16.0 * pow(ratio, (double)l));

    unsigned total = (unsigned)N_POINTS * N_LEVELS;   // 8388608 threads
    dim3 block(256);
    dim3 grid(total / 256);
    hashenc_kernel<<<grid, block>>>(inputs, emb, offs, out, sc);
}